// round 11
// baseline (speedup 1.0000x reference)
#include <cuda_runtime.h>

// ZBL pair energy + segment-sum into per-atom energies.
//
// Inputs (metadata order; JAX default x64-off stores "int64" as int32):
//   d_in[0] Z               float32 [4]
//   d_in[1] r               float32 [E]          (E = 6,400,000)
//   d_in[2] per_atom_energy float32 [n_atoms,1]  (n_atoms = 100,000)
//   d_in[3] atom_types      int32   [n_atoms]
//   d_in[4] edge_index      int32   [2, E]
// Output: float32 [n_atoms, 1]

#define ZBL_QQ        7.1998225f        // 14.399645 * 0.5
#define ZBL_INV_A0    (1.0f / 0.4685f)
#define ZBL_INV_RMAX  (1.0f / 6.0f)
#define LOG2E         1.4426950408889634f
#define ZBL_D1 (-0.20162f)
#define ZBL_D2 (-0.40290f)
#define ZBL_D3 (-0.94229f)
#define ZBL_D4 (-3.19980f)

#define NTHREADS 256
#define BLOCKS_PER_SM 7
#define NBLOCKS  (BLOCKS_PER_SM * 152)   // 1064: exactly one wave

// Shared-memory LUT capacity: 6400 words * 16 types = 102400 atoms.
#define SMEM_WORDS 6400
// Fallback global packed buffer: 1M words = 16M atoms (4MB static).
#define MAX_PACK_WORDS (1 << 20)
__device__ unsigned g_packed_types[MAX_PACK_WORDS];

__device__ __forceinline__ float ex2_approx(float x) {
    float y; asm("ex2.approx.f32 %0, %1;" : "=f"(y) : "f"(x)); return y;
}
__device__ __forceinline__ float rcp_approx(float x) {
    float y; asm("rcp.approx.f32 %0, %1;" : "=f"(y) : "f"(x)); return y;
}

// Fused prep: out = per_atom_energy (float4 copy) AND pack types 2-bit/atom.
__global__ void prep_kernel(const float* __restrict__ pae,
                            float* __restrict__ out,
                            const int* __restrict__ types,
                            int n_atoms, int n_words)
{
    const int i = blockIdx.x * blockDim.x + threadIdx.x;
    const int nvec4 = n_atoms >> 2;

    if (i < nvec4)
        reinterpret_cast<float4*>(out)[i] =
            reinterpret_cast<const float4*>(pae)[i];
    if (i == 0)
        for (int a = nvec4 << 2; a < n_atoms; a++) out[a] = pae[a];

    if (i < n_words) {
        unsigned v = 0;
        const int base = i << 4;
        if (base + 16 <= n_atoms) {
            const int4* t4 = reinterpret_cast<const int4*>(types + base);
            #pragma unroll
            for (int q = 0; q < 4; q++) {
                int4 w = t4[q];
                v |= ((unsigned)w.x & 3u) << ((q * 4 + 0) * 2);
                v |= ((unsigned)w.y & 3u) << ((q * 4 + 1) * 2);
                v |= ((unsigned)w.z & 3u) << ((q * 4 + 2) * 2);
                v |= ((unsigned)w.w & 3u) << ((q * 4 + 3) * 2);
            }
        } else {
            for (int k = 0; k < 16; k++) {
                int a = base + k;
                unsigned t = (a < n_atoms) ? ((unsigned)types[a] & 3u) : 0u;
                v |= t << (k * 2);
            }
        }
        g_packed_types[i] = v;
    }
}

// One edge, branchless except the predicated atomic. Short live ranges.
__device__ __forceinline__ void edge1(const unsigned* __restrict__ tbl,
                                      const float2* __restrict__ s_pair,
                                      float* __restrict__ out,
                                      float rk, int ie, int je)
{
    const bool live = rk < 6.0f;
    const int ia = live ? ie : 0;     // dead lanes read word 0 (broadcast, ~free)
    const int ja = live ? je : 0;
    const unsigned wi = tbl[ia >> 4];
    const unsigned wj = tbl[ja >> 4];
    const int ti = (wi >> ((ia & 15) << 1)) & 3;
    const int tj = (wj >> ((ja & 15) << 1)) & 3;
    const float2 pr = s_pair[(ti << 2) | tj];

    const float brk = pr.x * rk;
    const float e1 = ex2_approx(ZBL_D1 * brk);
    const float e2 = ex2_approx(ZBL_D2 * brk);
    const float e3 = ex2_approx(ZBL_D3 * brk);
    const float e4 = ex2_approx(ZBL_D4 * brk);
    float psi = fmaf(0.02817f, e1,
                fmaf(0.28022f, e2,
                fmaf(0.50986f, e3, 0.18175f * e4)));

    // Polynomial cutoff, p=6: 1 - 28 rr^6 + 48 rr^7 - 21 rr^8
    const float rr  = rk * ZBL_INV_RMAX;
    const float rr2 = rr * rr;
    const float rr3 = rr2 * rr;
    const float rr6 = rr3 * rr3;
    const float cut = fmaf(rr6, fmaf(rr, fmaf(rr, -21.0f, 48.0f), -28.0f), 1.0f);

    const float eng = pr.y * psi * rcp_approx(rk) * cut;
    if (live) atomicAdd(&out[ie], eng);
}

// Per-edge ZBL energy. 4 edges/thread/iter, software-pipelined (depth 2).
template <bool USE_SMEM>
__global__ void __launch_bounds__(NTHREADS, BLOCKS_PER_SM)
zbl_edge_kernel(const float* __restrict__ r,
                const int* __restrict__ e_i,
                const int* __restrict__ e_j,
                const float* __restrict__ Z,
                float* __restrict__ out,
                int E, int n_words)
{
    __shared__ unsigned s_pack[USE_SMEM ? SMEM_WORDS : 1];
    // Per-pair: x = (Zi^0.23 + Zj^0.23)/a0 * log2e,  y = QQ*Zi*Zj
    __shared__ float2 s_pair[16];
    __shared__ float s_zp[4], s_z[4];

    const int tid = threadIdx.x;
    if (tid < 4) {
        float z = Z[tid];
        s_z[tid]  = z;
        s_zp[tid] = __powf(z, 0.23f);
    }
    __syncthreads();
    if (tid < 16) {
        int ti = tid >> 2, tj = tid & 3;
        s_pair[tid] = make_float2(
            (s_zp[ti] + s_zp[tj]) * ZBL_INV_A0 * LOG2E,
            ZBL_QQ * s_z[ti] * s_z[tj]);
    }
    if (USE_SMEM) {
        for (int w = tid; w < n_words; w += NTHREADS)
            s_pack[w] = g_packed_types[w];
    }
    __syncthreads();

    const unsigned* __restrict__ tbl = USE_SMEM ? s_pack : g_packed_types;

    const int nvec   = E >> 2;
    const int stride = gridDim.x * blockDim.x;
    int t = blockIdx.x * blockDim.x + tid;

    if (t < nvec) {
        // Prologue: load first tile.
        float4 r4 = __ldcs(reinterpret_cast<const float4*>(r) + t);
        int4   i4 = __ldcs(reinterpret_cast<const int4*>(e_i) + t);
        int4   j4 = __ldcs(reinterpret_cast<const int4*>(e_j) + t);

        for (;;) {
            const int tn = t + stride;
            const bool more = tn < nvec;

            // Prefetch next tile before computing current (latency overlap).
            float4 r4n; int4 i4n, j4n;
            if (more) {
                r4n = __ldcs(reinterpret_cast<const float4*>(r) + tn);
                i4n = __ldcs(reinterpret_cast<const int4*>(e_i) + tn);
                j4n = __ldcs(reinterpret_cast<const int4*>(e_j) + tn);
            }

            edge1(tbl, s_pair, out, r4.x, i4.x, j4.x);
            edge1(tbl, s_pair, out, r4.y, i4.y, j4.y);
            edge1(tbl, s_pair, out, r4.z, i4.z, j4.z);
            edge1(tbl, s_pair, out, r4.w, i4.w, j4.w);

            if (!more) break;
            r4 = r4n; i4 = i4n; j4 = j4n; t = tn;
        }
    }

    // Scalar tail (E not divisible by 4): at most 3 edges, one thread.
    if (blockIdx.x == 0 && tid == 0) {
        for (int e = nvec << 2; e < E; e++) {
            float rk = r[e];
            if (rk >= 6.0f) continue;
            int i = e_i[e], j = e_j[e];
            unsigned wi = tbl[i >> 4];
            unsigned wj = tbl[j >> 4];
            int ti = (wi >> ((i & 15) << 1)) & 3;
            int tj = (wj >> ((j & 15) << 1)) & 3;
            float2 pr = s_pair[(ti << 2) | tj];
            float brk = pr.x * rk;
            float e1 = ex2_approx(ZBL_D1 * brk);
            float e2 = ex2_approx(ZBL_D2 * brk);
            float e3 = ex2_approx(ZBL_D3 * brk);
            float e4 = ex2_approx(ZBL_D4 * brk);
            float psi = fmaf(0.02817f, e1,
                        fmaf(0.28022f, e2,
                        fmaf(0.50986f, e3, 0.18175f * e4)));
            float rr  = rk * ZBL_INV_RMAX;
            float rr2 = rr * rr;
            float rr6 = rr2 * rr2 * rr2;
            float cut = fmaf(rr6, fmaf(rr, fmaf(rr, -21.0f, 48.0f), -28.0f), 1.0f);
            float eng = pr.y * psi * rcp_approx(rk);
            atomicAdd(&out[i], eng * cut);
        }
    }
}

extern "C" void kernel_launch(void* const* d_in, const int* in_sizes, int n_in,
                              void* d_out, int out_size)
{
    const float* Z     = (const float*)d_in[0];
    const float* r     = (const float*)d_in[1];
    const float* pae   = (const float*)d_in[2];
    const int*   types = (const int*)d_in[3];
    const int*   eidx  = (const int*)d_in[4];
    float*       out   = (float*)d_out;

    const int E       = in_sizes[1];
    const int n_atoms = in_sizes[2];
    const int n_words = (n_atoms + 15) >> 4;

    {
        int work = (n_atoms >> 2) > n_words ? (n_atoms >> 2) : n_words;
        if (work < 1) work = 1;
        prep_kernel<<<(work + 255) / 256, 256>>>(pae, out, types, n_atoms, n_words);
    }

    if (n_words <= SMEM_WORDS) {
        zbl_edge_kernel<true><<<NBLOCKS, NTHREADS>>>(r, eidx, eidx + E, Z, out, E, n_words);
    } else {
        zbl_edge_kernel<false><<<NBLOCKS, NTHREADS>>>(r, eidx, eidx + E, Z, out, E, n_words);
    }
}

// round 12
// speedup vs baseline: 1.0188x; 1.0188x over previous
#include <cuda_runtime.h>

// ZBL pair energy + segment-sum into per-atom energies.
//
// Inputs (metadata order; JAX default x64-off stores "int64" as int32):
//   d_in[0] Z               float32 [4]
//   d_in[1] r               float32 [E]          (E = 6,400,000)
//   d_in[2] per_atom_energy float32 [n_atoms,1]  (n_atoms = 100,000)
//   d_in[3] atom_types      int32   [n_atoms]
//   d_in[4] edge_index      int32   [2, E]
// Output: float32 [n_atoms, 1]

#define ZBL_QQ        7.1998225f        // 14.399645 * 0.5
#define ZBL_INV_A0    (1.0f / 0.4685f)
#define ZBL_INV_RMAX  (1.0f / 6.0f)
#define LOG2E         1.4426950408889634f
#define ZBL_D1 (-0.20162f)
#define ZBL_D2 (-0.40290f)
#define ZBL_D3 (-0.94229f)
#define ZBL_D4 (-3.19980f)

#define NTHREADS 256
#define NBLOCKS  912      // 6 blocks/SM (40 regs) x 152 SMs: exactly one wave

// Shared-memory LUT capacity: 6400 words * 16 types = 102400 atoms.
#define SMEM_WORDS 6400
// Fallback global packed buffer: 1M words = 16M atoms (4MB static).
#define MAX_PACK_WORDS (1 << 20)
__device__ unsigned g_packed_types[MAX_PACK_WORDS];

__device__ __forceinline__ float ex2_approx(float x) {
    float y; asm("ex2.approx.f32 %0, %1;" : "=f"(y) : "f"(x)); return y;
}
__device__ __forceinline__ float rcp_approx(float x) {
    float y; asm("rcp.approx.f32 %0, %1;" : "=f"(y) : "f"(x)); return y;
}
__device__ __forceinline__ void prefetch_l2(const void* p) {
    asm volatile("prefetch.global.L2 [%0];" :: "l"(p));
}

// Fused prep: out = per_atom_energy (float4 copy) AND pack types 2-bit/atom.
__global__ void prep_kernel(const float* __restrict__ pae,
                            float* __restrict__ out,
                            const int* __restrict__ types,
                            int n_atoms, int n_words)
{
    const int i = blockIdx.x * blockDim.x + threadIdx.x;
    const int nvec4 = n_atoms >> 2;

    if (i < nvec4)
        reinterpret_cast<float4*>(out)[i] =
            reinterpret_cast<const float4*>(pae)[i];
    if (i == 0)
        for (int a = nvec4 << 2; a < n_atoms; a++) out[a] = pae[a];

    if (i < n_words) {
        unsigned v = 0;
        const int base = i << 4;
        if (base + 16 <= n_atoms) {
            const int4* t4 = reinterpret_cast<const int4*>(types + base);
            #pragma unroll
            for (int q = 0; q < 4; q++) {
                int4 w = t4[q];
                v |= ((unsigned)w.x & 3u) << ((q * 4 + 0) * 2);
                v |= ((unsigned)w.y & 3u) << ((q * 4 + 1) * 2);
                v |= ((unsigned)w.z & 3u) << ((q * 4 + 2) * 2);
                v |= ((unsigned)w.w & 3u) << ((q * 4 + 3) * 2);
            }
        } else {
            for (int k = 0; k < 16; k++) {
                int a = base + k;
                unsigned t = (a < n_atoms) ? ((unsigned)types[a] & 3u) : 0u;
                v |= t << (k * 2);
            }
        }
        g_packed_types[i] = v;
    }
}

// One edge, branchless except the predicated atomic. Short live ranges.
__device__ __forceinline__ void edge1(const unsigned* __restrict__ tbl,
                                      const float2* __restrict__ s_pair,
                                      float* __restrict__ out,
                                      float rk, int ie, int je)
{
    const bool live = rk < 6.0f;
    const int ia = live ? ie : 0;     // dead lanes read word 0 (broadcast, ~free)
    const int ja = live ? je : 0;
    const unsigned wi = tbl[ia >> 4];
    const unsigned wj = tbl[ja >> 4];
    const int ti = (wi >> ((ia & 15) << 1)) & 3;
    const int tj = (wj >> ((ja & 15) << 1)) & 3;
    const float2 pr = s_pair[(ti << 2) | tj];

    const float brk = pr.x * rk;
    const float e1 = ex2_approx(ZBL_D1 * brk);
    const float e2 = ex2_approx(ZBL_D2 * brk);
    const float e3 = ex2_approx(ZBL_D3 * brk);
    const float e4 = ex2_approx(ZBL_D4 * brk);
    float psi = fmaf(0.02817f, e1,
                fmaf(0.28022f, e2,
                fmaf(0.50986f, e3, 0.18175f * e4)));

    // Polynomial cutoff, p=6: 1 - 28 rr^6 + 48 rr^7 - 21 rr^8
    const float rr  = rk * ZBL_INV_RMAX;
    const float rr2 = rr * rr;
    const float rr3 = rr2 * rr;
    const float rr6 = rr3 * rr3;
    const float cut = fmaf(rr6, fmaf(rr, fmaf(rr, -21.0f, 48.0f), -28.0f), 1.0f);

    const float eng = pr.y * psi * rcp_approx(rk) * cut;
    if (live) atomicAdd(&out[ie], eng);
}

// Per-edge ZBL energy. 4 edges/thread/iter.
// Two-level pipeline: L2 prefetch 2 iterations ahead, register prefetch 1 ahead.
template <bool USE_SMEM>
__global__ void __launch_bounds__(NTHREADS)
zbl_edge_kernel(const float* __restrict__ r,
                const int* __restrict__ e_i,
                const int* __restrict__ e_j,
                const float* __restrict__ Z,
                float* __restrict__ out,
                int E, int n_words)
{
    __shared__ unsigned s_pack[USE_SMEM ? SMEM_WORDS : 1];
    // Per-pair: x = (Zi^0.23 + Zj^0.23)/a0 * log2e,  y = QQ*Zi*Zj
    __shared__ float2 s_pair[16];
    __shared__ float s_zp[4], s_z[4];

    const int tid = threadIdx.x;
    if (tid < 4) {
        float z = Z[tid];
        s_z[tid]  = z;
        s_zp[tid] = __powf(z, 0.23f);
    }
    __syncthreads();
    if (tid < 16) {
        int ti = tid >> 2, tj = tid & 3;
        s_pair[tid] = make_float2(
            (s_zp[ti] + s_zp[tj]) * ZBL_INV_A0 * LOG2E,
            ZBL_QQ * s_z[ti] * s_z[tj]);
    }
    if (USE_SMEM) {
        for (int w = tid; w < n_words; w += NTHREADS)
            s_pack[w] = g_packed_types[w];
    }
    __syncthreads();

    const unsigned* __restrict__ tbl = USE_SMEM ? s_pack : g_packed_types;

    const int nvec   = E >> 2;
    const int stride = gridDim.x * blockDim.x;
    int t = blockIdx.x * blockDim.x + tid;

    if (t < nvec) {
        // Prologue: load first tile; L2-prefetch the second.
        float4 r4 = __ldcs(reinterpret_cast<const float4*>(r) + t);
        int4   i4 = __ldcs(reinterpret_cast<const int4*>(e_i) + t);
        int4   j4 = __ldcs(reinterpret_cast<const int4*>(e_j) + t);
        if (t + stride < nvec) {
            prefetch_l2(reinterpret_cast<const float4*>(r) + t + stride);
            prefetch_l2(reinterpret_cast<const int4*>(e_i) + t + stride);
            prefetch_l2(reinterpret_cast<const int4*>(e_j) + t + stride);
        }

        for (;;) {
            const int tn = t + stride;
            const bool more = tn < nvec;

            // L2 prefetch 2 ahead (no register cost).
            const int tp = tn + stride;
            if (tp < nvec) {
                prefetch_l2(reinterpret_cast<const float4*>(r) + tp);
                prefetch_l2(reinterpret_cast<const int4*>(e_i) + tp);
                prefetch_l2(reinterpret_cast<const int4*>(e_j) + tp);
            }

            // Register prefetch 1 ahead (should hit L2 thanks to the above).
            float4 r4n; int4 i4n, j4n;
            if (more) {
                r4n = __ldcs(reinterpret_cast<const float4*>(r) + tn);
                i4n = __ldcs(reinterpret_cast<const int4*>(e_i) + tn);
                j4n = __ldcs(reinterpret_cast<const int4*>(e_j) + tn);
            }

            edge1(tbl, s_pair, out, r4.x, i4.x, j4.x);
            edge1(tbl, s_pair, out, r4.y, i4.y, j4.y);
            edge1(tbl, s_pair, out, r4.z, i4.z, j4.z);
            edge1(tbl, s_pair, out, r4.w, i4.w, j4.w);

            if (!more) break;
            r4 = r4n; i4 = i4n; j4 = j4n; t = tn;
        }
    }

    // Scalar tail (E not divisible by 4): at most 3 edges, one thread.
    if (blockIdx.x == 0 && tid == 0) {
        for (int e = nvec << 2; e < E; e++) {
            float rk = r[e];
            if (rk >= 6.0f) continue;
            int i = e_i[e], j = e_j[e];
            unsigned wi = tbl[i >> 4];
            unsigned wj = tbl[j >> 4];
            int ti = (wi >> ((i & 15) << 1)) & 3;
            int tj = (wj >> ((j & 15) << 1)) & 3;
            float2 pr = s_pair[(ti << 2) | tj];
            float brk = pr.x * rk;
            float e1 = ex2_approx(ZBL_D1 * brk);
            float e2 = ex2_approx(ZBL_D2 * brk);
            float e3 = ex2_approx(ZBL_D3 * brk);
            float e4 = ex2_approx(ZBL_D4 * brk);
            float psi = fmaf(0.02817f, e1,
                        fmaf(0.28022f, e2,
                        fmaf(0.50986f, e3, 0.18175f * e4)));
            float rr  = rk * ZBL_INV_RMAX;
            float rr2 = rr * rr;
            float rr6 = rr2 * rr2 * rr2;
            float cut = fmaf(rr6, fmaf(rr, fmaf(rr, -21.0f, 48.0f), -28.0f), 1.0f);
            float eng = pr.y * psi * rcp_approx(rk);
            atomicAdd(&out[i], eng * cut);
        }
    }
}

extern "C" void kernel_launch(void* const* d_in, const int* in_sizes, int n_in,
                              void* d_out, int out_size)
{
    const float* Z     = (const float*)d_in[0];
    const float* r     = (const float*)d_in[1];
    const float* pae   = (const float*)d_in[2];
    const int*   types = (const int*)d_in[3];
    const int*   eidx  = (const int*)d_in[4];
    float*       out   = (float*)d_out;

    const int E       = in_sizes[1];
    const int n_atoms = in_sizes[2];
    const int n_words = (n_atoms + 15) >> 4;

    {
        int work = (n_atoms >> 2) > n_words ? (n_atoms >> 2) : n_words;
        if (work < 1) work = 1;
        prep_kernel<<<(work + 255) / 256, 256>>>(pae, out, types, n_atoms, n_words);
    }

    if (n_words <= SMEM_WORDS) {
        zbl_edge_kernel<true><<<NBLOCKS, NTHREADS>>>(r, eidx, eidx + E, Z, out, E, n_words);
    } else {
        zbl_edge_kernel<false><<<NBLOCKS, NTHREADS>>>(r, eidx, eidx + E, Z, out, E, n_words);
    }
}

// round 13
// speedup vs baseline: 1.0814x; 1.0614x over previous
#include <cuda_runtime.h>

// ZBL pair energy + segment-sum into per-atom energies.
//
// Inputs (metadata order; JAX default x64-off stores "int64" as int32):
//   d_in[0] Z               float32 [4]
//   d_in[1] r               float32 [E]          (E = 6,400,000)
//   d_in[2] per_atom_energy float32 [n_atoms,1]  (n_atoms = 100,000)
//   d_in[3] atom_types      int32   [n_atoms]
//   d_in[4] edge_index      int32   [2, E]
// Output: float32 [n_atoms, 1]
//
// Regime (established R5-R12): kernel is LSU-throughput bound
// (REDG 6.8M cyc + LDS 2.4M + LDG 0.6M ≈ 34us floor). Do not add LSU ops.

#define ZBL_QQ        7.1998225f        // 14.399645 * 0.5
#define ZBL_INV_A0    (1.0f / 0.4685f)
#define ZBL_INV_RMAX  (1.0f / 6.0f)
#define LOG2E         1.4426950408889634f
#define ZBL_D1 (-0.20162f)
#define ZBL_D2 (-0.40290f)
#define ZBL_D3 (-0.94229f)
#define ZBL_D4 (-3.19980f)

#define NTHREADS 256
#define NBLOCKS  1216     // R9-proven best grid

// Shared-memory LUT capacity: 6400 words * 16 types = 102400 atoms.
#define SMEM_WORDS 6400
// Fallback global packed buffer: 1M words = 16M atoms (4MB static).
#define MAX_PACK_WORDS (1 << 20)
__device__ unsigned g_packed_types[MAX_PACK_WORDS];

__device__ __forceinline__ float ex2_approx(float x) {
    float y; asm("ex2.approx.f32 %0, %1;" : "=f"(y) : "f"(x)); return y;
}
__device__ __forceinline__ float rcp_approx(float x) {
    float y; asm("rcp.approx.f32 %0, %1;" : "=f"(y) : "f"(x)); return y;
}

// Fused prep: out = per_atom_energy (float4 copy) AND pack types 2-bit/atom.
__global__ void prep_kernel(const float* __restrict__ pae,
                            float* __restrict__ out,
                            const int* __restrict__ types,
                            int n_atoms, int n_words)
{
    const int i = blockIdx.x * blockDim.x + threadIdx.x;
    const int nvec4 = n_atoms >> 2;

    if (i < nvec4)
        reinterpret_cast<float4*>(out)[i] =
            reinterpret_cast<const float4*>(pae)[i];
    if (i == 0)
        for (int a = nvec4 << 2; a < n_atoms; a++) out[a] = pae[a];

    if (i < n_words) {
        unsigned v = 0;
        const int base = i << 4;
        if (base + 16 <= n_atoms) {
            const int4* t4 = reinterpret_cast<const int4*>(types + base);
            #pragma unroll
            for (int q = 0; q < 4; q++) {
                int4 w = t4[q];
                v |= ((unsigned)w.x & 3u) << ((q * 4 + 0) * 2);
                v |= ((unsigned)w.y & 3u) << ((q * 4 + 1) * 2);
                v |= ((unsigned)w.z & 3u) << ((q * 4 + 2) * 2);
                v |= ((unsigned)w.w & 3u) << ((q * 4 + 3) * 2);
            }
        } else {
            for (int k = 0; k < 16; k++) {
                int a = base + k;
                unsigned t = (a < n_atoms) ? ((unsigned)types[a] & 3u) : 0u;
                v |= t << (k * 2);
            }
        }
        g_packed_types[i] = v;
    }
}

// Per-edge ZBL energy. 4 edges/thread/iter, depth-2 register pipeline,
// type-LDS batched right after index arrival (max LDS-to-use distance).
template <bool USE_SMEM>
__global__ void __launch_bounds__(NTHREADS)
zbl_edge_kernel(const float* __restrict__ r,
                const int* __restrict__ e_i,
                const int* __restrict__ e_j,
                const float* __restrict__ Z,
                float* __restrict__ out,
                int E, int n_words)
{
    __shared__ unsigned s_pack[USE_SMEM ? SMEM_WORDS : 1];
    // Per-pair: x = (Zi^0.23 + Zj^0.23)/a0 * log2e,  y = QQ*Zi*Zj
    __shared__ float2 s_pair[16];
    __shared__ float s_zp[4], s_z[4];

    const int tid = threadIdx.x;
    if (tid < 4) {
        float z = Z[tid];
        s_z[tid]  = z;
        s_zp[tid] = __powf(z, 0.23f);
    }
    __syncthreads();
    if (tid < 16) {
        int ti = tid >> 2, tj = tid & 3;
        s_pair[tid] = make_float2(
            (s_zp[ti] + s_zp[tj]) * ZBL_INV_A0 * LOG2E,
            ZBL_QQ * s_z[ti] * s_z[tj]);
    }
    if (USE_SMEM) {
        for (int w = tid; w < n_words; w += NTHREADS)
            s_pack[w] = g_packed_types[w];
    }
    __syncthreads();

    const unsigned* __restrict__ tbl = USE_SMEM ? s_pack : g_packed_types;

    const int nvec   = E >> 2;
    const int stride = gridDim.x * blockDim.x;
    int t = blockIdx.x * blockDim.x + tid;

    if (t < nvec) {
        // Prologue: load first tile.
        float4 r4 = __ldcs(reinterpret_cast<const float4*>(r) + t);
        int4   i4 = __ldcs(reinterpret_cast<const int4*>(e_i) + t);
        int4   j4 = __ldcs(reinterpret_cast<const int4*>(e_j) + t);

        for (;;) {
            const int tn = t + stride;
            const bool more = tn < nvec;

            // Register prefetch 1 iteration ahead (proven win, R9).
            float4 r4n; int4 i4n, j4n;
            if (more) {
                r4n = __ldcs(reinterpret_cast<const float4*>(r) + tn);
                i4n = __ldcs(reinterpret_cast<const int4*>(e_i) + tn);
                j4n = __ldcs(reinterpret_cast<const int4*>(e_j) + tn);
            }

            const int   ii[4] = {i4.x, i4.y, i4.z, i4.w};
            const int   jj[4] = {j4.x, j4.y, j4.z, j4.w};
            const float rv[4] = {r4.x, r4.y, r4.z, r4.w};

            // Phase 1: batch ALL shared-memory lookups (8 type LDS + 4 pair
            // LDS.64) so their 29-cyc latency overlaps across edges.
            bool   live[4];
            float2 pr[4];
            #pragma unroll
            for (int k = 0; k < 4; k++) {
                live[k] = rv[k] < 6.0f;
                const int ia = live[k] ? ii[k] : 0;  // dead lanes: broadcast word 0
                const int ja = live[k] ? jj[k] : 0;
                const unsigned wi = tbl[ia >> 4];
                const unsigned wj = tbl[ja >> 4];
                const int ti = (wi >> ((ia & 15) << 1)) & 3;
                const int tj = (wj >> ((ja & 15) << 1)) & 3;
                pr[k] = s_pair[(ti << 2) | tj];
            }

            // Phase 2: math + predicated atomic per edge.
            #pragma unroll
            for (int k = 0; k < 4; k++) {
                const float rk = rv[k];
                const float brk = pr[k].x * rk;
                const float e1 = ex2_approx(ZBL_D1 * brk);
                const float e2 = ex2_approx(ZBL_D2 * brk);
                const float e3 = ex2_approx(ZBL_D3 * brk);
                const float e4 = ex2_approx(ZBL_D4 * brk);
                float psi = fmaf(0.02817f, e1,
                            fmaf(0.28022f, e2,
                            fmaf(0.50986f, e3, 0.18175f * e4)));

                // Cutoff, p=6: 1 - 28 rr^6 + 48 rr^7 - 21 rr^8
                const float rr  = rk * ZBL_INV_RMAX;
                const float rr2 = rr * rr;
                const float rr3 = rr2 * rr;
                const float rr6 = rr3 * rr3;
                const float cut = fmaf(rr6, fmaf(rr, fmaf(rr, -21.0f, 48.0f), -28.0f), 1.0f);

                const float eng = pr[k].y * psi * rcp_approx(rk) * cut;
                if (live[k]) atomicAdd(&out[ii[k]], eng);
            }

            if (!more) break;
            r4 = r4n; i4 = i4n; j4 = j4n; t = tn;
        }
    }

    // Scalar tail (E not divisible by 4): at most 3 edges, one thread.
    if (blockIdx.x == 0 && tid == 0) {
        for (int e = nvec << 2; e < E; e++) {
            float rk = r[e];
            if (rk >= 6.0f) continue;
            int i = e_i[e], j = e_j[e];
            unsigned wi = tbl[i >> 4];
            unsigned wj = tbl[j >> 4];
            int ti = (wi >> ((i & 15) << 1)) & 3;
            int tj = (wj >> ((j & 15) << 1)) & 3;
            float2 pr = s_pair[(ti << 2) | tj];
            float brk = pr.x * rk;
            float e1 = ex2_approx(ZBL_D1 * brk);
            float e2 = ex2_approx(ZBL_D2 * brk);
            float e3 = ex2_approx(ZBL_D3 * brk);
            float e4 = ex2_approx(ZBL_D4 * brk);
            float psi = fmaf(0.02817f, e1,
                        fmaf(0.28022f, e2,
                        fmaf(0.50986f, e3, 0.18175f * e4)));
            float rr  = rk * ZBL_INV_RMAX;
            float rr2 = rr * rr;
            float rr6 = rr2 * rr2 * rr2;
            float cut = fmaf(rr6, fmaf(rr, fmaf(rr, -21.0f, 48.0f), -28.0f), 1.0f);
            float eng = pr.y * psi * rcp_approx(rk);
            atomicAdd(&out[i], eng * cut);
        }
    }
}

extern "C" void kernel_launch(void* const* d_in, const int* in_sizes, int n_in,
                              void* d_out, int out_size)
{
    const float* Z     = (const float*)d_in[0];
    const float* r     = (const float*)d_in[1];
    const float* pae   = (const float*)d_in[2];
    const int*   types = (const int*)d_in[3];
    const int*   eidx  = (const int*)d_in[4];
    float*       out   = (float*)d_out;

    const int E       = in_sizes[1];
    const int n_atoms = in_sizes[2];
    const int n_words = (n_atoms + 15) >> 4;

    {
        int work = (n_atoms >> 2) > n_words ? (n_atoms >> 2) : n_words;
        if (work < 1) work = 1;
        prep_kernel<<<(work + 255) / 256, 256>>>(pae, out, types, n_atoms, n_words);
    }

    if (n_words <= SMEM_WORDS) {
        zbl_edge_kernel<true><<<NBLOCKS, NTHREADS>>>(r, eidx, eidx + E, Z, out, E, n_words);
    } else {
        zbl_edge_kernel<false><<<NBLOCKS, NTHREADS>>>(r, eidx, eidx + E, Z, out, E, n_words);
    }
}

// round 14
// speedup vs baseline: 1.0880x; 1.0062x over previous
#include <cuda_runtime.h>

// ZBL pair energy + segment-sum into per-atom energies.
//
// Inputs (metadata order; JAX default x64-off stores "int64" as int32):
//   d_in[0] Z               float32 [4]
//   d_in[1] r               float32 [E]          (E = 6,400,000)
//   d_in[2] per_atom_energy float32 [n_atoms,1]  (n_atoms = 100,000)
//   d_in[3] atom_types      int32   [n_atoms]
//   d_in[4] edge_index      int32   [2, E]
// Output: float32 [n_atoms, 1]
//
// Regime (R5-R13): L1tex/LSU bound (REDG ~22us + LDS + LDG) with residual
// DRAM stream latency exposure. Depth-2 register pipeline proven (+6us, R9);
// this round: depth-3 (covers ~340cyc of the ~600cyc DRAM latency).

#define ZBL_QQ        7.1998225f        // 14.399645 * 0.5
#define ZBL_INV_A0    (1.0f / 0.4685f)
#define ZBL_INV_RMAX  (1.0f / 6.0f)
#define LOG2E         1.4426950408889634f
#define ZBL_D1 (-0.20162f)
#define ZBL_D2 (-0.40290f)
#define ZBL_D3 (-0.94229f)
#define ZBL_D4 (-3.19980f)

#define NTHREADS 256
#define NBLOCKS  1216

// Shared-memory LUT capacity: 6400 words * 16 types = 102400 atoms.
#define SMEM_WORDS 6400
// Fallback global packed buffer: 1M words = 16M atoms (4MB static).
#define MAX_PACK_WORDS (1 << 20)
__device__ unsigned g_packed_types[MAX_PACK_WORDS];

__device__ __forceinline__ float ex2_approx(float x) {
    float y; asm("ex2.approx.f32 %0, %1;" : "=f"(y) : "f"(x)); return y;
}
__device__ __forceinline__ float rcp_approx(float x) {
    float y; asm("rcp.approx.f32 %0, %1;" : "=f"(y) : "f"(x)); return y;
}

// Fused prep: out = per_atom_energy (float4 copy) AND pack types 2-bit/atom.
__global__ void prep_kernel(const float* __restrict__ pae,
                            float* __restrict__ out,
                            const int* __restrict__ types,
                            int n_atoms, int n_words)
{
    const int i = blockIdx.x * blockDim.x + threadIdx.x;
    const int nvec4 = n_atoms >> 2;

    if (i < nvec4)
        reinterpret_cast<float4*>(out)[i] =
            reinterpret_cast<const float4*>(pae)[i];
    if (i == 0)
        for (int a = nvec4 << 2; a < n_atoms; a++) out[a] = pae[a];

    if (i < n_words) {
        unsigned v = 0;
        const int base = i << 4;
        if (base + 16 <= n_atoms) {
            const int4* t4 = reinterpret_cast<const int4*>(types + base);
            #pragma unroll
            for (int q = 0; q < 4; q++) {
                int4 w = t4[q];
                v |= ((unsigned)w.x & 3u) << ((q * 4 + 0) * 2);
                v |= ((unsigned)w.y & 3u) << ((q * 4 + 1) * 2);
                v |= ((unsigned)w.z & 3u) << ((q * 4 + 2) * 2);
                v |= ((unsigned)w.w & 3u) << ((q * 4 + 3) * 2);
            }
        } else {
            for (int k = 0; k < 16; k++) {
                int a = base + k;
                unsigned t = (a < n_atoms) ? ((unsigned)types[a] & 3u) : 0u;
                v |= t << (k * 2);
            }
        }
        g_packed_types[i] = v;
    }
}

// Per-edge ZBL energy. 4 edges/thread/iter, depth-3 register pipeline.
template <bool USE_SMEM>
__global__ void __launch_bounds__(NTHREADS)
zbl_edge_kernel(const float* __restrict__ r,
                const int* __restrict__ e_i,
                const int* __restrict__ e_j,
                const float* __restrict__ Z,
                float* __restrict__ out,
                int E, int n_words)
{
    __shared__ unsigned s_pack[USE_SMEM ? SMEM_WORDS : 1];
    // Per-pair: x = (Zi^0.23 + Zj^0.23)/a0 * log2e,  y = QQ*Zi*Zj
    __shared__ float2 s_pair[16];
    __shared__ float s_zp[4], s_z[4];

    const int tid = threadIdx.x;
    if (tid < 4) {
        float z = Z[tid];
        s_z[tid]  = z;
        s_zp[tid] = __powf(z, 0.23f);
    }
    __syncthreads();
    if (tid < 16) {
        int ti = tid >> 2, tj = tid & 3;
        s_pair[tid] = make_float2(
            (s_zp[ti] + s_zp[tj]) * ZBL_INV_A0 * LOG2E,
            ZBL_QQ * s_z[ti] * s_z[tj]);
    }
    if (USE_SMEM) {
        for (int w = tid; w < n_words; w += NTHREADS)
            s_pack[w] = g_packed_types[w];
    }
    __syncthreads();

    const unsigned* __restrict__ tbl = USE_SMEM ? s_pack : g_packed_types;

    const int nvec   = E >> 2;
    const int stride = gridDim.x * blockDim.x;
    int t0 = blockIdx.x * blockDim.x + tid;

    if (t0 < nvec) {
        // Prologue: stage A (compute-next) and stage B (1 ahead).
        float4 rA = __ldcs(reinterpret_cast<const float4*>(r) + t0);
        int4   iA = __ldcs(reinterpret_cast<const int4*>(e_i) + t0);
        int4   jA = __ldcs(reinterpret_cast<const int4*>(e_j) + t0);

        int  t1   = t0 + stride;
        bool hasB = t1 < nvec;
        float4 rB; int4 iB, jB;
        if (hasB) {
            rB = __ldcs(reinterpret_cast<const float4*>(r) + t1);
            iB = __ldcs(reinterpret_cast<const int4*>(e_i) + t1);
            jB = __ldcs(reinterpret_cast<const int4*>(e_j) + t1);
        }

        for (;;) {
            // Stage C: load 2 iterations ahead.
            const int  t2   = t1 + stride;
            const bool hasC = hasB && (t2 < nvec);
            float4 rC; int4 iC, jC;
            if (hasC) {
                rC = __ldcs(reinterpret_cast<const float4*>(r) + t2);
                iC = __ldcs(reinterpret_cast<const int4*>(e_i) + t2);
                jC = __ldcs(reinterpret_cast<const int4*>(e_j) + t2);
            }

            // Compute stage A.
            {
                const int   ii[4] = {iA.x, iA.y, iA.z, iA.w};
                const int   jj[4] = {jA.x, jA.y, jA.z, jA.w};
                const float rv[4] = {rA.x, rA.y, rA.z, rA.w};

                // Phase 1: batch all smem lookups (latency overlap).
                bool   live[4];
                float2 pr[4];
                #pragma unroll
                for (int k = 0; k < 4; k++) {
                    live[k] = rv[k] < 6.0f;
                    const int ia = live[k] ? ii[k] : 0;  // dead: broadcast word 0
                    const int ja = live[k] ? jj[k] : 0;
                    const unsigned wi = tbl[ia >> 4];
                    const unsigned wj = tbl[ja >> 4];
                    const int ti = (wi >> ((ia & 15) << 1)) & 3;
                    const int tj = (wj >> ((ja & 15) << 1)) & 3;
                    pr[k] = s_pair[(ti << 2) | tj];
                }

                // Phase 2: math + predicated atomic per edge.
                #pragma unroll
                for (int k = 0; k < 4; k++) {
                    const float rk = rv[k];
                    const float brk = pr[k].x * rk;
                    const float e1 = ex2_approx(ZBL_D1 * brk);
                    const float e2 = ex2_approx(ZBL_D2 * brk);
                    const float e3 = ex2_approx(ZBL_D3 * brk);
                    const float e4 = ex2_approx(ZBL_D4 * brk);
                    float psi = fmaf(0.02817f, e1,
                                fmaf(0.28022f, e2,
                                fmaf(0.50986f, e3, 0.18175f * e4)));

                    // Cutoff, p=6: 1 - 28 rr^6 + 48 rr^7 - 21 rr^8
                    const float rr  = rk * ZBL_INV_RMAX;
                    const float rr2 = rr * rr;
                    const float rr3 = rr2 * rr;
                    const float rr6 = rr3 * rr3;
                    const float cut = fmaf(rr6,
                        fmaf(rr, fmaf(rr, -21.0f, 48.0f), -28.0f), 1.0f);

                    const float eng = pr[k].y * psi * rcp_approx(rk) * cut;
                    if (live[k]) atomicAdd(&out[ii[k]], eng);
                }
            }

            if (!hasB) break;
            // Rotate pipeline stages.
            rA = rB; iA = iB; jA = jB;
            rB = rC; iB = iC; jB = jC;
            t1 = t2; hasB = hasC;
        }
    }

    // Scalar tail (E not divisible by 4): at most 3 edges, one thread.
    if (blockIdx.x == 0 && tid == 0) {
        for (int e = nvec << 2; e < E; e++) {
            float rk = r[e];
            if (rk >= 6.0f) continue;
            int i = e_i[e], j = e_j[e];
            unsigned wi = tbl[i >> 4];
            unsigned wj = tbl[j >> 4];
            int ti = (wi >> ((i & 15) << 1)) & 3;
            int tj = (wj >> ((j & 15) << 1)) & 3;
            float2 pr = s_pair[(ti << 2) | tj];
            float brk = pr.x * rk;
            float e1 = ex2_approx(ZBL_D1 * brk);
            float e2 = ex2_approx(ZBL_D2 * brk);
            float e3 = ex2_approx(ZBL_D3 * brk);
            float e4 = ex2_approx(ZBL_D4 * brk);
            float psi = fmaf(0.02817f, e1,
                        fmaf(0.28022f, e2,
                        fmaf(0.50986f, e3, 0.18175f * e4)));
            float rr  = rk * ZBL_INV_RMAX;
            float rr2 = rr * rr;
            float rr6 = rr2 * rr2 * rr2;
            float cut = fmaf(rr6, fmaf(rr, fmaf(rr, -21.0f, 48.0f), -28.0f), 1.0f);
            float eng = pr.y * psi * rcp_approx(rk);
            atomicAdd(&out[i], eng * cut);
        }
    }
}

extern "C" void kernel_launch(void* const* d_in, const int* in_sizes, int n_in,
                              void* d_out, int out_size)
{
    const float* Z     = (const float*)d_in[0];
    const float* r     = (const float*)d_in[1];
    const float* pae   = (const float*)d_in[2];
    const int*   types = (const int*)d_in[3];
    const int*   eidx  = (const int*)d_in[4];
    float*       out   = (float*)d_out;

    const int E       = in_sizes[1];
    const int n_atoms = in_sizes[2];
    const int n_words = (n_atoms + 15) >> 4;

    {
        int work = (n_atoms >> 2) > n_words ? (n_atoms >> 2) : n_words;
        if (work < 1) work = 1;
        prep_kernel<<<(work + 255) / 256, 256>>>(pae, out, types, n_atoms, n_words);
    }

    if (n_words <= SMEM_WORDS) {
        zbl_edge_kernel<true><<<NBLOCKS, NTHREADS>>>(r, eidx, eidx + E, Z, out, E, n_words);
    } else {
        zbl_edge_kernel<false><<<NBLOCKS, NTHREADS>>>(r, eidx, eidx + E, Z, out, E, n_words);
    }
}